// round 16
// baseline (speedup 1.0000x reference)
#include <cuda_runtime.h>
#include <cuda_fp16.h>
#include <math.h>
#include <stdint.h>

// Problem constants
#define B_ 4
#define S_ 4096
#define D_ 1024
#define M_ (B_*S_)   // 16384

// ---------------- scratch (__device__ globals; no cudaMalloc allowed) ----------------
__device__ __half g_X[(size_t)M_*D_];          // conv(inputs)  fp16
__device__ __half g_Ctx[(size_t)M_*D_];        // conv(context) fp16
__device__ __half g_q[(size_t)M_*D_];          // q_phi [B*S, D]
__device__ __half g_kT[(size_t)M_*D_];         // k_phi^T [B,D,S]
__device__ __half g_vT[(size_t)M_*D_];         // v^T [B,D,S]
__device__ __half g_kvT[(size_t)B_*D_*D_];     // kv^T [B,E,D]
__device__ __half g_att[(size_t)M_*D_];        // att [B*S, D]
__device__ __half g_Wqt[(size_t)D_*D_];        // weights^T fp16
__device__ __half g_Wkt[(size_t)D_*D_];
__device__ __half g_Wvt[(size_t)D_*D_];
__device__ __half g_Wot[(size_t)D_*D_];
__device__ float g_ksum[B_*D_];
__device__ float g_z[M_];

// ---------------- PTX helpers (portable sm_80+ subset only; NO tcgen05) ----------------
static __device__ __forceinline__ uint32_t smem_u32(const void* p){
    uint32_t a;
    asm("{ .reg .u64 t; cvta.to.shared.u64 t, %1; cvt.u32.u64 %0, t; }" : "=r"(a) : "l"(p));
    return a;
}
static __device__ __forceinline__ void cp_async16(uint32_t dst, const void* src){
    asm volatile("cp.async.cg.shared.global [%0], [%1], 16;" :: "r"(dst), "l"(src) : "memory");
}
static __device__ __forceinline__ void cp_commit(){
    asm volatile("cp.async.commit_group;" ::: "memory");
}
template<int N>
static __device__ __forceinline__ void cp_wait(){
    asm volatile("cp.async.wait_group %0;" :: "n"(N) : "memory");
}
static __device__ __forceinline__ void ldsm4(uint32_t* r, uint32_t addr){
    asm volatile("ldmatrix.sync.aligned.m8n8.x4.shared.b16 {%0,%1,%2,%3}, [%4];"
                 : "=r"(r[0]), "=r"(r[1]), "=r"(r[2]), "=r"(r[3]) : "r"(addr));
}
// fp16 HMMA, fp32 accumulate
static __device__ __forceinline__ void mma16816(float* d, const uint32_t* a, const uint32_t* b){
    asm volatile("mma.sync.aligned.m16n8k16.row.col.f32.f16.f16.f32 "
                 "{%0,%1,%2,%3}, {%4,%5,%6,%7}, {%8,%9}, {%0,%1,%2,%3};"
                 : "+f"(d[0]), "+f"(d[1]), "+f"(d[2]), "+f"(d[3])
                 : "r"(a[0]), "r"(a[1]), "r"(a[2]), "r"(a[3]), "r"(b[0]), "r"(b[1]));
}

// CTA tile 128(M) x 256(N), BK=64. Stage = A 16K | B 32K = 48KB; x2 = 96KB, 1 CTA/SM
#define STAGE_BYTES 49152
#define SMEM_ALLOC  (2*STAGE_BYTES)    // 96KB; HALFT staging 128x264 fp16 = 67.6KB fits
#define NTHREADS    256

// Output modes
#define OUT_F32    0
#define OUT_HALF   1   // row-major fp16
#define OUT_HALFT  2   // transposed fp16

// ---------------- HMMA GEMM: C[m,n] = sum_k A[m,k]*B[n,k] ----------------
// A, B single fp16, BOTH K-major. Single pass.
// 128x256 CTA tile, 8 warps 2x4, warp tile 64x64 (acc 128 regs), BK=64.
template<int ACT, bool HAS_Z, bool HAS_RES, int OUT>
__global__ __launch_bounds__(NTHREADS, 1)
void mma_gemm(const __half* __restrict__ Ag, long sA,
              const __half* __restrict__ Bg, long sB,
              float* __restrict__ Cf, __half* __restrict__ Cp, long sC,
              const float* __restrict__ bias,
              const float* __restrict__ Zall, long sZ,
              const float* __restrict__ Rall, long sR,
              int N, int K,
              long sBatchT, int ldT, int rowShift, int rowMask)
{
    extern __shared__ char smem[];
    const uint32_t sbase = smem_u32(smem);
    const int tid  = threadIdx.x;
    const int wid  = tid >> 5;
    const int lane = tid & 31;
    const int warp_m = wid >> 2;      // 0..1 -> 64 rows each
    const int warp_n = wid & 3;       // 0..3 -> 64 cols each

    const __half* A  = Ag + (long)blockIdx.z * sA;
    const __half* Bp = Bg + (long)blockIdx.z * sB;
    const long rowBase = (long)blockIdx.y * 128;
    const long colBase = (long)blockIdx.x * 256;

    // ---- stage loader: A 128x64 + B 256x64 fp16, XOR-swizzled 16B chunks ----
    auto load_stage = [&](int t, int s){
        const long k0 = (long)t * 64;
        const uint32_t dstbase = sbase + (uint32_t)s * STAGE_BYTES;
        {   // A: 1024 chunks
            const __half* sp = A + rowBase * K + k0;
            #pragma unroll
            for (int j = 0; j < 4; ++j){
                const int id  = tid + j * 256;
                const int row = id >> 3, c = id & 7;
                cp_async16(dstbase + (((row << 3) + (c ^ (row & 7))) << 4),
                           sp + (long)row * K + c * 8);
            }
        }
        {   // B: 2048 chunks at +16384
            const __half* sp = Bp + colBase * K + k0;
            const uint32_t db = dstbase + 16384;
            #pragma unroll
            for (int j = 0; j < 8; ++j){
                const int id  = tid + j * 256;
                const int row = id >> 3, c = id & 7;
                cp_async16(db + (((row << 3) + (c ^ (row & 7))) << 4),
                           sp + (long)row * K + c * 8);
            }
        }
    };

    float acc[4][8][4];
    #pragma unroll
    for (int a = 0; a < 4; ++a)
        #pragma unroll
        for (int b = 0; b < 8; ++b)
            #pragma unroll
            for (int c = 0; c < 4; ++c) acc[a][b][c] = 0.f;

    const int r16 = lane & 15, cs = lane >> 4;   // ldmatrix addressing

    const int nT = K / 64;
    load_stage(0, 0);
    cp_commit();

    uint32_t stc = sbase;
    for (int t = 0; t < nT; ++t){
        if (t + 1 < nT){ load_stage(t + 1, (t + 1) & 1); cp_commit(); cp_wait<1>(); }
        else           { cp_wait<0>(); }
        __syncthreads();
        #pragma unroll
        for (int kk = 0; kk < 4; ++kk){
            const int kc = kk * 2 + cs;          // 16B chunk index along k
            uint32_t ah[4][4], bh[8][2];
            #pragma unroll
            for (int mf = 0; mf < 4; ++mf){
                const int row = warp_m * 64 + mf * 16 + r16;
                const uint32_t off = ((row << 3) + (kc ^ (row & 7))) << 4;
                ldsm4(ah[mf], stc + off);                  // A subtile
            }
            #pragma unroll
            for (int p = 0; p < 4; ++p){
                const int row = warp_n * 64 + p * 16 + r16;
                const uint32_t off = ((row << 3) + (kc ^ (row & 7))) << 4;
                uint32_t t0[4];
                ldsm4(t0, stc + 16384 + off);              // B subtile
                bh[p*2+0][0] = t0[0]; bh[p*2+1][0] = t0[1];
                bh[p*2+0][1] = t0[2]; bh[p*2+1][1] = t0[3];
            }
            #pragma unroll
            for (int mf = 0; mf < 4; ++mf)
                #pragma unroll
                for (int nf = 0; nf < 8; ++nf) mma16816(acc[mf][nf], ah[mf], bh[nf]);
        }
        __syncthreads();
        stc = sbase + (uint32_t)((t + 1) & 1) * STAGE_BYTES;
    }

    // ---- epilogue ----
    const int gr = lane >> 2, gc = (lane & 3) * 2;
    const float* Z = HAS_Z   ? (Zall + (long)blockIdx.z * sZ) : nullptr;
    const float* R = HAS_RES ? (Rall + (long)blockIdx.z * sR) : nullptr;

    if (OUT == OUT_HALFT){
        __half* ts = (__half*)smem;   // 128 x 264 fp16 = 67.6KB
        #pragma unroll
        for (int mf = 0; mf < 4; ++mf){
            #pragma unroll
            for (int h = 0; h < 2; ++h){
                const int rl = warp_m * 64 + mf * 16 + gr + h * 8;
                #pragma unroll
                for (int nf = 0; nf < 8; ++nf){
                    const int cl = warp_n * 64 + nf * 8 + gc;
                    float v0 = acc[mf][nf][h*2+0];
                    float v1 = acc[mf][nf][h*2+1];
                    if (bias){ v0 += bias[colBase + cl]; v1 += bias[colBase + cl + 1]; }
                    if (ACT == 1){
                        v0 = (v0 > 0.f) ? (v0 + 1.f) : __expf(v0);
                        v1 = (v1 > 0.f) ? (v1 + 1.f) : __expf(v1);
                    }
                    __half2 hp; hp.x = __float2half(v0); hp.y = __float2half(v1);
                    *(__half2*)&ts[rl * 264 + cl] = hp;
                }
            }
        }
        __syncthreads();
        // write transposed: out row n = tid (0..255), 128 m each
        const int r   = tid;
        const int bb  = (int)(rowBase >> rowShift);
        const long mo = rowBase & rowMask;
        __half* dh = Cp + (long)blockIdx.z * sC + (long)bb * sBatchT
                   + (colBase + r) * (long)ldT + mo;
        #pragma unroll
        for (int j = 0; j < 128; j += 2){
            __half2 hp;
            hp.x = ts[(j    ) * 264 + r];
            hp.y = ts[(j + 1) * 264 + r];
            *(__half2*)(dh + j) = hp;
        }
        return;
    }

    #pragma unroll
    for (int mf = 0; mf < 4; ++mf){
        #pragma unroll
        for (int h = 0; h < 2; ++h){
            const long row = rowBase + warp_m * 64 + mf * 16 + gr + h * 8;
            const float zs = HAS_Z ? Z[row] : 1.f;
            #pragma unroll
            for (int nf = 0; nf < 8; ++nf){
                const long col = colBase + warp_n * 64 + nf * 8 + gc;
                float v0 = acc[mf][nf][h*2+0];
                float v1 = acc[mf][nf][h*2+1];
                if (bias){ v0 += bias[col]; v1 += bias[col+1]; }
                if (ACT == 1){
                    v0 = (v0 > 0.f) ? (v0 + 1.f) : __expf(v0);
                    v1 = (v1 > 0.f) ? (v1 + 1.f) : __expf(v1);
                }
                if (HAS_Z){ v0 *= zs; v1 *= zs; }
                if (HAS_RES){
                    float2 rr = *(const float2*)(R + row * (long)N + col);
                    v0 += rr.x; v1 += rr.y;
                }
                if (OUT == OUT_HALF){
                    __half2 hp; hp.x = __float2half(v0); hp.y = __float2half(v1);
                    *(__half2*)((Cp + (long)blockIdx.z * sC) + row * (long)N + col) = hp;
                } else {
                    *(float2*)((Cf + (long)blockIdx.z * sC) + row * (long)N + col) = make_float2(v0, v1);
                }
            }
        }
    }
}

// ---------------- convert fp32 -> fp16 ----------------
__global__ __launch_bounds__(256)
void conv_kernel(const float* __restrict__ in, __half* __restrict__ hi, int n4)
{
    int i = blockIdx.x * 256 + threadIdx.x;
    if (i >= n4) return;
    float4 x = ((const float4*)in)[i];
    __half2 h0, h1;
    h0.x = __float2half(x.x); h0.y = __float2half(x.y);
    h1.x = __float2half(x.z); h1.y = __float2half(x.w);
    ((__half2*)hi)[2*i]   = h0; ((__half2*)hi)[2*i+1] = h1;
}

// ---------------- fused weight transpose+convert: 4x fp32 [D,D] -> fp16 [D,D]^T ----------------
__global__ __launch_bounds__(256)
void wtconv_kernel(const float* __restrict__ W0, const float* __restrict__ W1,
                   const float* __restrict__ W2, const float* __restrict__ W3,
                   __half* __restrict__ h0, __half* __restrict__ h1,
                   __half* __restrict__ h2, __half* __restrict__ h3)
{
    __shared__ float t[32][33];
    const float* src; __half* dh;
    switch (blockIdx.z){
        case 0:  src = W0; dh = h0; break;
        case 1:  src = W1; dh = h1; break;
        case 2:  src = W2; dh = h2; break;
        default: src = W3; dh = h3; break;
    }
    const int x = blockIdx.x * 32, y = blockIdx.y * 32;
    #pragma unroll
    for (int j = 0; j < 4; ++j)
        t[threadIdx.y + 8*j][threadIdx.x] = src[(long)(y + threadIdx.y + 8*j) * D_ + x + threadIdx.x];
    __syncthreads();
    #pragma unroll
    for (int j = 0; j < 4; ++j){
        float v = t[threadIdx.x][threadIdx.y + 8*j];
        long o = (long)(x + threadIdx.y + 8*j) * D_ + y + threadIdx.x;
        dh[o] = __float2half(v);
    }
}

// ---------------- ksum from kT: ksum[b*D+d] = sum_s kT[b,d,s] ----------------
__global__ __launch_bounds__(256)
void ksumT_kernel(const __half* __restrict__ kT, float* __restrict__ ksum)
{
    const int row  = blockIdx.x * 8 + (threadIdx.x >> 5);   // 0..4095
    const int lane = threadIdx.x & 31;
    const __half2* h2 = (const __half2*)(kT + (long)row * S_);
    float acc = 0.f;
    #pragma unroll 4
    for (int i = lane; i < S_/2; i += 32){
        __half2 h = h2[i];
        acc += __half2float(h.x) + __half2float(h.y);
    }
    #pragma unroll
    for (int o = 16; o > 0; o >>= 1) acc += __shfl_down_sync(0xffffffffu, acc, o);
    if (lane == 0) ksum[row] = acc;
}

// ---------------- z[b,s] = 1/(q_phi . ksum + 1e-6) ----------------
__global__ void z_kernel(const __half* __restrict__ q,
                         const float* __restrict__ ksum, float* __restrict__ z)
{
    const int s = blockIdx.x, b = blockIdx.y;
    const __half2* q2 = (const __half2*)(q + ((long)b * S_ + s) * D_);
    const float2* k2 = (const float2*)(ksum + (long)b * D_);
    float acc = 0.f;
    for (int i = threadIdx.x; i < D_ / 2; i += 128){
        __half2 h = q2[i];
        float2 kk = k2[i];
        acc += __half2float(h.x) * kk.x + __half2float(h.y) * kk.y;
    }
    #pragma unroll
    for (int o = 16; o > 0; o >>= 1) acc += __shfl_down_sync(0xffffffffu, acc, o);
    __shared__ float sm[4];
    if ((threadIdx.x & 31) == 0) sm[threadIdx.x >> 5] = acc;
    __syncthreads();
    if (threadIdx.x == 0)
        z[(long)b * S_ + s] = 1.f / (sm[0] + sm[1] + sm[2] + sm[3] + 1e-6f);
}

// ---------------- launcher ----------------
extern "C" void kernel_launch(void* const* d_in, const int* in_sizes, int n_in,
                              void* d_out, int out_size)
{
    const float* inputs  = (const float*)d_in[0];
    const float* context = (const float*)d_in[1];
    const float* Wq = (const float*)d_in[2]; const float* bq = (const float*)d_in[3];
    const float* Wk = (const float*)d_in[4]; const float* bk = (const float*)d_in[5];
    const float* Wv = (const float*)d_in[6]; const float* bv = (const float*)d_in[7];
    const float* Wo = (const float*)d_in[8]; const float* bo = (const float*)d_in[9];
    float* out = (float*)d_out;

    __half *X,*Ctx,*q,*kT,*vT,*kvT,*att,*Wqt,*Wkt,*Wvt,*Wot;
    float *ksum,*z;
    cudaGetSymbolAddress((void**)&X, g_X);       cudaGetSymbolAddress((void**)&Ctx, g_Ctx);
    cudaGetSymbolAddress((void**)&q, g_q);       cudaGetSymbolAddress((void**)&kT, g_kT);
    cudaGetSymbolAddress((void**)&vT, g_vT);     cudaGetSymbolAddress((void**)&kvT, g_kvT);
    cudaGetSymbolAddress((void**)&att, g_att);
    cudaGetSymbolAddress((void**)&Wqt, g_Wqt);   cudaGetSymbolAddress((void**)&Wkt, g_Wkt);
    cudaGetSymbolAddress((void**)&Wvt, g_Wvt);   cudaGetSymbolAddress((void**)&Wot, g_Wot);
    cudaGetSymbolAddress((void**)&ksum, g_ksum); cudaGetSymbolAddress((void**)&z, g_z);

    // opt-in to 96 KB dynamic smem for all GEMM instantiations
    cudaFuncSetAttribute(mma_gemm<1,false,false,OUT_HALF >, cudaFuncAttributeMaxDynamicSharedMemorySize, SMEM_ALLOC);
    cudaFuncSetAttribute(mma_gemm<1,false,false,OUT_HALFT>, cudaFuncAttributeMaxDynamicSharedMemorySize, SMEM_ALLOC);
    cudaFuncSetAttribute(mma_gemm<0,false,false,OUT_HALFT>, cudaFuncAttributeMaxDynamicSharedMemorySize, SMEM_ALLOC);
    cudaFuncSetAttribute(mma_gemm<0,true ,false,OUT_HALF >, cudaFuncAttributeMaxDynamicSharedMemorySize, SMEM_ALLOC);
    cudaFuncSetAttribute(mma_gemm<0,false,true ,OUT_F32  >, cudaFuncAttributeMaxDynamicSharedMemorySize, SMEM_ALLOC);

    const long MD = (long)M_ * D_;
    const long SD = (long)S_ * D_;
    const long DD = (long)D_ * D_;

    dim3 blk(NTHREADS);
    dim3 tb(32, 8);
    dim3 gProj(D_/256, M_/128, 1);   // 4 x 128

    // launch 0,1: convert activations to fp16
    conv_kernel<<<(int)(MD/4/256), 256>>>(inputs,  X,   (int)(MD/4));
    conv_kernel<<<(int)(MD/4/256), 256>>>(context, Ctx, (int)(MD/4));

    // launch 2: all 4 weight transposes fused
    wtconv_kernel<<<dim3(D_/32, D_/32, 4), tb>>>(Wq, Wk, Wv, Wo, Wqt, Wkt, Wvt, Wot);

    // launch 3: q_phi = phi(inputs Wq + bq) -> fp16 [B*S, D]
    mma_gemm<1,false,false,OUT_HALF><<<gProj, blk, SMEM_ALLOC>>>(
        X, 0, Wqt, 0, nullptr, q, 0, bq,
        nullptr, 0, nullptr, 0, D_, D_, 0, 0, 0, 0);

    // launch 4: k_phi = phi(context Wk + bk) -> TRANSPOSED fp16 [B, D, S]
    mma_gemm<1,false,false,OUT_HALFT><<<gProj, blk, SMEM_ALLOC>>>(
        Ctx, 0, Wkt, 0, nullptr, kT, 0, bk,
        nullptr, 0, nullptr, 0, D_, D_, (long)D_*S_, S_, 12, S_-1);

    // launch 5 (ncu capture target): v = context Wv + bv -> TRANSPOSED fp16 [B, D, S]
    mma_gemm<0,false,false,OUT_HALFT><<<gProj, blk, SMEM_ALLOC>>>(
        Ctx, 0, Wvt, 0, nullptr, vT, 0, bv,
        nullptr, 0, nullptr, 0, D_, D_, (long)D_*S_, S_, 12, S_-1);

    // launch 6,7: k_sum and z
    ksumT_kernel<<<(B_*D_)/8, 256>>>(kT, ksum);
    z_kernel<<<dim3(S_, B_), 128>>>(q, ksum, z);

    // launch 8: kv[b] = k^T v (A=kT [D,S], B=vT [D,S], K=S) -> TRANSPOSED fp16 kvT [B, E, D]
    mma_gemm<0,false,false,OUT_HALFT><<<dim3(D_/256, D_/128, B_), blk, SMEM_ALLOC>>>(
        kT, SD, vT, SD, nullptr, kvT, DD,
        nullptr, nullptr, 0, nullptr, 0, D_, S_, 0, D_, 30, D_-1);

    // launch 9: att[b] = (q kv) * z (A=q [S,D], B=kvT [E,D]) -> fp16 [B*S, D]
    mma_gemm<0,true,false,OUT_HALF><<<dim3(D_/256, S_/128, B_), blk, SMEM_ALLOC>>>(
        q, SD, kvT, DD, nullptr, att, SD,
        nullptr, z, (long)S_, nullptr, 0, D_, D_, 0, 0, 0, 0);

    // launch 10: out = att Wo + bo + inputs (fp32)
    mma_gemm<0,false,true,OUT_F32><<<gProj, blk, SMEM_ALLOC>>>(
        att, 0, Wot, 0, out, nullptr, 0,
        bo, nullptr, 0, inputs, 0, D_, D_, 0, 0, 0, 0);
}

// round 17
// speedup vs baseline: 1.1736x; 1.1736x over previous
#include <cuda_runtime.h>
#include <cuda_fp16.h>
#include <math.h>
#include <stdint.h>

// Problem constants
#define B_ 4
#define S_ 4096
#define D_ 1024
#define M_ (B_*S_)   // 16384

// ---------------- scratch (__device__ globals; no cudaMalloc allowed) ----------------
__device__ __half g_X[(size_t)M_*D_];          // conv(inputs)  fp16
__device__ __half g_Ctx[(size_t)M_*D_];        // conv(context) fp16
__device__ __half g_q[(size_t)M_*D_];          // q_phi [B*S, D]
__device__ __half g_kT[(size_t)M_*D_];         // k_phi^T [B,D,S]
__device__ __half g_vT[(size_t)M_*D_];         // v^T [B,D,S]
__device__ __half g_kvT[(size_t)B_*D_*D_];     // kv^T [B,E,D]
__device__ __half g_att[(size_t)M_*D_];        // att [B*S, D]
__device__ __half g_Wqt[(size_t)D_*D_];        // weights^T fp16
__device__ __half g_Wkt[(size_t)D_*D_];
__device__ __half g_Wvt[(size_t)D_*D_];
__device__ __half g_Wot[(size_t)D_*D_];
__device__ float g_ksum[B_*D_];
__device__ float g_z[M_];

// ---------------- PTX helpers (portable sm_80+ subset only; NO tcgen05) ----------------
static __device__ __forceinline__ uint32_t smem_u32(const void* p){
    uint32_t a;
    asm("{ .reg .u64 t; cvta.to.shared.u64 t, %1; cvt.u32.u64 %0, t; }" : "=r"(a) : "l"(p));
    return a;
}
static __device__ __forceinline__ void cp_async16(uint32_t dst, const void* src){
    asm volatile("cp.async.cg.shared.global [%0], [%1], 16;" :: "r"(dst), "l"(src) : "memory");
}
static __device__ __forceinline__ void cp_commit(){
    asm volatile("cp.async.commit_group;" ::: "memory");
}
template<int N>
static __device__ __forceinline__ void cp_wait(){
    asm volatile("cp.async.wait_group %0;" :: "n"(N) : "memory");
}
static __device__ __forceinline__ void ldsm4(uint32_t* r, uint32_t addr){
    asm volatile("ldmatrix.sync.aligned.m8n8.x4.shared.b16 {%0,%1,%2,%3}, [%4];"
                 : "=r"(r[0]), "=r"(r[1]), "=r"(r[2]), "=r"(r[3]) : "r"(addr));
}
// fp16 HMMA, fp32 accumulate
static __device__ __forceinline__ void mma16816(float* d, const uint32_t* a, const uint32_t* b){
    asm volatile("mma.sync.aligned.m16n8k16.row.col.f32.f16.f16.f32 "
                 "{%0,%1,%2,%3}, {%4,%5,%6,%7}, {%8,%9}, {%0,%1,%2,%3};"
                 : "+f"(d[0]), "+f"(d[1]), "+f"(d[2]), "+f"(d[3])
                 : "r"(a[0]), "r"(a[1]), "r"(a[2]), "r"(a[3]), "r"(b[0]), "r"(b[1]));
}

// BK=64. Stage = A 16K | B 16K = 32KB; double-buffered = 64KB/CTA -> 2 CTAs/SM
#define STAGE_BYTES 32768
#define SMEM_ALLOC  65536
#define NTHREADS    256

// Output modes
#define OUT_F32    0
#define OUT_HALF   1   // row-major fp16
#define OUT_HALFT  2   // transposed fp16

// ---------------- HMMA GEMM: C[m,n] = sum_k A[m,k]*B[n,k] ----------------
// A, B single fp16, BOTH K-major. Single pass.
// 128x128 CTA tile, 8 warps 2x4, warp tile 64x32, 2 CTAs/SM, single-buffered frags.
template<int ACT, bool HAS_Z, bool HAS_RES, int OUT>
__global__ __launch_bounds__(NTHREADS, 2)
void mma_gemm(const __half* __restrict__ Ag, long sA,
              const __half* __restrict__ Bg, long sB,
              float* __restrict__ Cf, __half* __restrict__ Cp, long sC,
              const float* __restrict__ bias,
              const float* __restrict__ Zall, long sZ,
              const float* __restrict__ Rall, long sR,
              int N, int K,
              long sBatchT, int ldT, int rowShift, int rowMask)
{
    extern __shared__ char smem[];
    const uint32_t sbase = smem_u32(smem);
    const int tid  = threadIdx.x;
    const int wid  = tid >> 5;
    const int lane = tid & 31;
    const int warp_m = wid >> 2;      // 0..1 -> 64 rows each
    const int warp_n = wid & 3;       // 0..3 -> 32 cols each

    const __half* A  = Ag + (long)blockIdx.z * sA;
    const __half* Bp = Bg + (long)blockIdx.z * sB;
    const long rowBase = (long)blockIdx.y * 128;
    const long colBase = (long)blockIdx.x * 128;

    // ---- stage loader: 2 subtiles, each 128 rows x 64 fp16, XOR-swizzled 16B chunks ----
    auto load_stage = [&](int t, int s){
        const long k0 = (long)t * 64;
        const uint32_t dstbase = sbase + (uint32_t)s * STAGE_BYTES;
        const __half* srcs[2] = { A + rowBase * K + k0, Bp + colBase * K + k0 };
        #pragma unroll
        for (int sub = 0; sub < 2; ++sub){
            const __half* sp = srcs[sub];
            const uint32_t db = dstbase + sub * 16384;
            #pragma unroll
            for (int j = 0; j < 4; ++j){
                const int id  = tid + j * 256;       // 0..1023 chunk id
                const int row = id >> 3, c = id & 7;
                const uint32_t daddr = db + (((row << 3) + (c ^ (row & 7))) << 4);
                cp_async16(daddr, sp + (long)row * K + c * 8);
            }
        }
    };

    float acc[4][4][4];
    #pragma unroll
    for (int a = 0; a < 4; ++a)
        #pragma unroll
        for (int b = 0; b < 4; ++b)
            #pragma unroll
            for (int c = 0; c < 4; ++c) acc[a][b][c] = 0.f;

    const int r16 = lane & 15, cs = lane >> 4;   // ldmatrix addressing

    const int nT = K / 64;
    load_stage(0, 0);
    cp_commit();

    uint32_t stc = sbase;
    for (int t = 0; t < nT; ++t){
        if (t + 1 < nT){ load_stage(t + 1, (t + 1) & 1); cp_commit(); cp_wait<1>(); }
        else           { cp_wait<0>(); }
        __syncthreads();
        #pragma unroll
        for (int kk = 0; kk < 4; ++kk){
            const int kc = kk * 2 + cs;          // 16B chunk index along k
            uint32_t ah[4][4], bh[4][2];
            #pragma unroll
            for (int mf = 0; mf < 4; ++mf){
                const int row = warp_m * 64 + mf * 16 + r16;
                const uint32_t off = ((row << 3) + (kc ^ (row & 7))) << 4;
                ldsm4(ah[mf], stc + off);            // A subtile at +0
            }
            #pragma unroll
            for (int p = 0; p < 2; ++p){
                const int row = warp_n * 32 + p * 16 + r16;
                const uint32_t off = ((row << 3) + (kc ^ (row & 7))) << 4;
                uint32_t t0[4];
                ldsm4(t0, stc + 16384 + off);        // B subtile
                bh[p*2+0][0] = t0[0]; bh[p*2+1][0] = t0[1];
                bh[p*2+0][1] = t0[2]; bh[p*2+1][1] = t0[3];
            }
            #pragma unroll
            for (int mf = 0; mf < 4; ++mf)
                #pragma unroll
                for (int nf = 0; nf < 4; ++nf) mma16816(acc[mf][nf], ah[mf], bh[nf]);
        }
        __syncthreads();
        stc = sbase + (uint32_t)((t + 1) & 1) * STAGE_BYTES;
    }

    // ---- epilogue ----
    const int gr = lane >> 2, gc = (lane & 3) * 2;
    const float* Z = HAS_Z   ? (Zall + (long)blockIdx.z * sZ) : nullptr;
    const float* R = HAS_RES ? (Rall + (long)blockIdx.z * sR) : nullptr;

    if (OUT == OUT_HALFT){
        __half* ts = (__half*)smem;   // 128 x 136 fp16 = 34.8KB <= 64KB
        #pragma unroll
        for (int mf = 0; mf < 4; ++mf){
            #pragma unroll
            for (int h = 0; h < 2; ++h){
                const int rl = warp_m * 64 + mf * 16 + gr + h * 8;
                #pragma unroll
                for (int nf = 0; nf < 4; ++nf){
                    const int cl = warp_n * 32 + nf * 8 + gc;
                    float v0 = acc[mf][nf][h*2+0];
                    float v1 = acc[mf][nf][h*2+1];
                    if (bias){ v0 += bias[colBase + cl]; v1 += bias[colBase + cl + 1]; }
                    if (ACT == 1){
                        v0 = (v0 > 0.f) ? (v0 + 1.f) : __expf(v0);
                        v1 = (v1 > 0.f) ? (v1 + 1.f) : __expf(v1);
                    }
                    __half2 hp; hp.x = __float2half(v0); hp.y = __float2half(v1);
                    *(__half2*)&ts[rl * 136 + cl] = hp;
                }
            }
        }
        __syncthreads();
        // write transposed: out row n = tid>>1 (0..127), 64 m each
        const int r   = tid >> 1;
        const int seg = (tid & 1) * 64;
        const int bb  = (int)((rowBase + seg) >> rowShift);
        const long mo = (rowBase + seg) & rowMask;
        __half* dh = Cp + (long)blockIdx.z * sC + (long)bb * sBatchT
                   + (colBase + r) * (long)ldT + mo;
        #pragma unroll
        for (int j = 0; j < 64; j += 2){
            __half2 hp;
            hp.x = ts[(seg + j    ) * 136 + r];
            hp.y = ts[(seg + j + 1) * 136 + r];
            *(__half2*)(dh + j) = hp;
        }
        return;
    }

    #pragma unroll
    for (int mf = 0; mf < 4; ++mf){
        #pragma unroll
        for (int h = 0; h < 2; ++h){
            const long row = rowBase + warp_m * 64 + mf * 16 + gr + h * 8;
            const float zs = HAS_Z ? Z[row] : 1.f;
            #pragma unroll
            for (int nf = 0; nf < 4; ++nf){
                const long col = colBase + warp_n * 32 + nf * 8 + gc;
                float v0 = acc[mf][nf][h*2+0];
                float v1 = acc[mf][nf][h*2+1];
                if (bias){ v0 += bias[col]; v1 += bias[col+1]; }
                if (ACT == 1){
                    v0 = (v0 > 0.f) ? (v0 + 1.f) : __expf(v0);
                    v1 = (v1 > 0.f) ? (v1 + 1.f) : __expf(v1);
                }
                if (HAS_Z){ v0 *= zs; v1 *= zs; }
                if (HAS_RES){
                    float2 rr = *(const float2*)(R + row * (long)N + col);
                    v0 += rr.x; v1 += rr.y;
                }
                if (OUT == OUT_HALF){
                    __half2 hp; hp.x = __float2half(v0); hp.y = __float2half(v1);
                    *(__half2*)((Cp + (long)blockIdx.z * sC) + row * (long)N + col) = hp;
                } else {
                    *(float2*)((Cf + (long)blockIdx.z * sC) + row * (long)N + col) = make_float2(v0, v1);
                }
            }
        }
    }
}

// ---------------- convert fp32 -> fp16 ----------------
__global__ __launch_bounds__(256)
void conv_kernel(const float* __restrict__ in, __half* __restrict__ hi, int n4)
{
    int i = blockIdx.x * 256 + threadIdx.x;
    if (i >= n4) return;
    float4 x = ((const float4*)in)[i];
    __half2 h0, h1;
    h0.x = __float2half(x.x); h0.y = __float2half(x.y);
    h1.x = __float2half(x.z); h1.y = __float2half(x.w);
    ((__half2*)hi)[2*i]   = h0; ((__half2*)hi)[2*i+1] = h1;
}

// ---------------- fused weight transpose+convert: 4x fp32 [D,D] -> fp16 [D,D]^T ----------------
__global__ __launch_bounds__(256)
void wtconv_kernel(const float* __restrict__ W0, const float* __restrict__ W1,
                   const float* __restrict__ W2, const float* __restrict__ W3,
                   __half* __restrict__ h0, __half* __restrict__ h1,
                   __half* __restrict__ h2, __half* __restrict__ h3)
{
    __shared__ float t[32][33];
    const float* src; __half* dh;
    switch (blockIdx.z){
        case 0:  src = W0; dh = h0; break;
        case 1:  src = W1; dh = h1; break;
        case 2:  src = W2; dh = h2; break;
        default: src = W3; dh = h3; break;
    }
    const int x = blockIdx.x * 32, y = blockIdx.y * 32;
    #pragma unroll
    for (int j = 0; j < 4; ++j)
        t[threadIdx.y + 8*j][threadIdx.x] = src[(long)(y + threadIdx.y + 8*j) * D_ + x + threadIdx.x];
    __syncthreads();
    #pragma unroll
    for (int j = 0; j < 4; ++j){
        float v = t[threadIdx.x][threadIdx.y + 8*j];
        long o = (long)(x + threadIdx.y + 8*j) * D_ + y + threadIdx.x;
        dh[o] = __float2half(v);
    }
}

// ---------------- ksum from kT: ksum[b*D+d] = sum_s kT[b,d,s] ----------------
__global__ __launch_bounds__(256)
void ksumT_kernel(const __half* __restrict__ kT, float* __restrict__ ksum)
{
    const int row  = blockIdx.x * 8 + (threadIdx.x >> 5);   // 0..4095
    const int lane = threadIdx.x & 31;
    const __half2* h2 = (const __half2*)(kT + (long)row * S_);
    float acc = 0.f;
    #pragma unroll 4
    for (int i = lane; i < S_/2; i += 32){
        __half2 h = h2[i];
        acc += __half2float(h.x) + __half2float(h.y);
    }
    #pragma unroll
    for (int o = 16; o > 0; o >>= 1) acc += __shfl_down_sync(0xffffffffu, acc, o);
    if (lane == 0) ksum[row] = acc;
}

// ---------------- z[b,s] = 1/(q_phi . ksum + 1e-6) ----------------
__global__ void z_kernel(const __half* __restrict__ q,
                         const float* __restrict__ ksum, float* __restrict__ z)
{
    const int s = blockIdx.x, b = blockIdx.y;
    const __half2* q2 = (const __half2*)(q + ((long)b * S_ + s) * D_);
    const float2* k2 = (const float2*)(ksum + (long)b * D_);
    float acc = 0.f;
    for (int i = threadIdx.x; i < D_ / 2; i += 128){
        __half2 h = q2[i];
        float2 kk = k2[i];
        acc += __half2float(h.x) * kk.x + __half2float(h.y) * kk.y;
    }
    #pragma unroll
    for (int o = 16; o > 0; o >>= 1) acc += __shfl_down_sync(0xffffffffu, acc, o);
    __shared__ float sm[4];
    if ((threadIdx.x & 31) == 0) sm[threadIdx.x >> 5] = acc;
    __syncthreads();
    if (threadIdx.x == 0)
        z[(long)b * S_ + s] = 1.f / (sm[0] + sm[1] + sm[2] + sm[3] + 1e-6f);
}

// ---------------- launcher ----------------
extern "C" void kernel_launch(void* const* d_in, const int* in_sizes, int n_in,
                              void* d_out, int out_size)
{
    const float* inputs  = (const float*)d_in[0];
    const float* context = (const float*)d_in[1];
    const float* Wq = (const float*)d_in[2]; const float* bq = (const float*)d_in[3];
    const float* Wk = (const float*)d_in[4]; const float* bk = (const float*)d_in[5];
    const float* Wv = (const float*)d_in[6]; const float* bv = (const float*)d_in[7];
    const float* Wo = (const float*)d_in[8]; const float* bo = (const float*)d_in[9];
    float* out = (float*)d_out;

    __half *X,*Ctx,*q,*kT,*vT,*kvT,*att,*Wqt,*Wkt,*Wvt,*Wot;
    float *ksum,*z;
    cudaGetSymbolAddress((void**)&X, g_X);       cudaGetSymbolAddress((void**)&Ctx, g_Ctx);
    cudaGetSymbolAddress((void**)&q, g_q);       cudaGetSymbolAddress((void**)&kT, g_kT);
    cudaGetSymbolAddress((void**)&vT, g_vT);     cudaGetSymbolAddress((void**)&kvT, g_kvT);
    cudaGetSymbolAddress((void**)&att, g_att);
    cudaGetSymbolAddress((void**)&Wqt, g_Wqt);   cudaGetSymbolAddress((void**)&Wkt, g_Wkt);
    cudaGetSymbolAddress((void**)&Wvt, g_Wvt);   cudaGetSymbolAddress((void**)&Wot, g_Wot);
    cudaGetSymbolAddress((void**)&ksum, g_ksum); cudaGetSymbolAddress((void**)&z, g_z);

    // opt-in to 64 KB dynamic smem for all GEMM instantiations
    cudaFuncSetAttribute(mma_gemm<1,false,false,OUT_HALF >, cudaFuncAttributeMaxDynamicSharedMemorySize, SMEM_ALLOC);
    cudaFuncSetAttribute(mma_gemm<1,false,false,OUT_HALFT>, cudaFuncAttributeMaxDynamicSharedMemorySize, SMEM_ALLOC);
    cudaFuncSetAttribute(mma_gemm<0,false,false,OUT_HALFT>, cudaFuncAttributeMaxDynamicSharedMemorySize, SMEM_ALLOC);
    cudaFuncSetAttribute(mma_gemm<0,true ,false,OUT_HALF >, cudaFuncAttributeMaxDynamicSharedMemorySize, SMEM_ALLOC);
    cudaFuncSetAttribute(mma_gemm<0,false,true ,OUT_F32  >, cudaFuncAttributeMaxDynamicSharedMemorySize, SMEM_ALLOC);

    const long MD = (long)M_ * D_;
    const long SD = (long)S_ * D_;
    const long DD = (long)D_ * D_;

    dim3 blk(NTHREADS);
    dim3 tb(32, 8);
    dim3 gProj(D_/128, M_/128, 1);

    // launch 0,1: convert activations to fp16
    conv_kernel<<<(int)(MD/4/256), 256>>>(inputs,  X,   (int)(MD/4));
    conv_kernel<<<(int)(MD/4/256), 256>>>(context, Ctx, (int)(MD/4));

    // launch 2: all 4 weight transposes fused
    wtconv_kernel<<<dim3(D_/32, D_/32, 4), tb>>>(Wq, Wk, Wv, Wo, Wqt, Wkt, Wvt, Wot);

    // launch 3: q_phi = phi(inputs Wq + bq) -> fp16 [B*S, D]
    mma_gemm<1,false,false,OUT_HALF><<<gProj, blk, SMEM_ALLOC>>>(
        X, 0, Wqt, 0, nullptr, q, 0, bq,
        nullptr, 0, nullptr, 0, D_, D_, 0, 0, 0, 0);

    // launch 4: k_phi = phi(context Wk + bk) -> TRANSPOSED fp16 [B, D, S]
    mma_gemm<1,false,false,OUT_HALFT><<<gProj, blk, SMEM_ALLOC>>>(
        Ctx, 0, Wkt, 0, nullptr, kT, 0, bk,
        nullptr, 0, nullptr, 0, D_, D_, (long)D_*S_, S_, 12, S_-1);

    // launch 5 (ncu capture target): v = context Wv + bv -> TRANSPOSED fp16 [B, D, S]
    mma_gemm<0,false,false,OUT_HALFT><<<gProj, blk, SMEM_ALLOC>>>(
        Ctx, 0, Wvt, 0, nullptr, vT, 0, bv,
        nullptr, 0, nullptr, 0, D_, D_, (long)D_*S_, S_, 12, S_-1);

    // launch 6,7: k_sum and z
    ksumT_kernel<<<(B_*D_)/8, 256>>>(kT, ksum);
    z_kernel<<<dim3(S_, B_), 128>>>(q, ksum, z);

    // launch 8: kv[b] = k^T v (A=kT [D,S], B=vT [D,S], K=S) -> TRANSPOSED fp16 kvT [B, E, D]
    mma_gemm<0,false,false,OUT_HALFT><<<dim3(D_/128, D_/128, B_), blk, SMEM_ALLOC>>>(
        kT, SD, vT, SD, nullptr, kvT, DD,
        nullptr, nullptr, 0, nullptr, 0, D_, S_, 0, D_, 30, D_-1);

    // launch 9: att[b] = (q kv) * z (A=q [S,D], B=kvT [E,D]) -> fp16 [B*S, D]
    mma_gemm<0,true,false,OUT_HALF><<<dim3(D_/128, S_/128, B_), blk, SMEM_ALLOC>>>(
        q, SD, kvT, DD, nullptr, att, SD,
        nullptr, z, (long)S_, nullptr, 0, D_, D_, 0, 0, 0, 0);

    // launch 10: out = att Wo + bo + inputs (fp32)
    mma_gemm<0,false,true,OUT_F32><<<gProj, blk, SMEM_ALLOC>>>(
        att, 0, Wot, 0, out, nullptr, 0,
        bo, nullptr, 0, inputs, 0, D_, D_, 0, 0, 0, 0);
}